// round 13
// baseline (speedup 1.0000x reference)
#include <cuda_runtime.h>
#include <cstddef>
#include <cstdint>

#define H     2048
#define B     1024
#define NB    12
#define NROW  112
#define GATES 8192
#define NBLK  128                 // persistent blocks (1/SM)
#define NTHR  512
#define KC4   192                 // float4 k-prefix of each W_hh row in smem (j<6)
#define JR0   6                   // register-resident j range [JR0, JR1)
#define JR1   10
#define JS0   10                  // streamed j range [JS0, 16)

// persist dynamic smem layout (floats)
#define WC_F      (64 * KC4 * 4)
#define SCAND_F   (2 * 704)
#define SDEC_F    (114 * 16)
#define SH_OFF_F  (WC_F + SCAND_F + SDEC_F)
#define P_DSMEM   ((SH_OFF_F + 2048) * 4)       // 217728 B

// k_pre dynamic smem
#define PRE_W_F2   (256 * 17)
#define PRE_E_F2   (56 * 17)
#define PRE_DSMEM  ((PRE_W_F2 + PRE_E_F2) * 8)

// ---------------------------------------------------------------------------
__device__ __align__(16) float g_h[2][H];
__device__ __align__(16) float g_c[H];
__device__ __align__(16) float g_pre[4][NROW][GATES];   // k-quarter partials
__device__ float g_part[2][12][NBLK];
__device__ unsigned g_cnt[32 * 8];

__device__ __forceinline__ float sigmoidf_(float v) { return 1.0f / (1.0f + expf(-v)); }

__device__ __forceinline__ void fma2(unsigned long long& d,
                                     unsigned long long a, unsigned long long b) {
    asm("fma.rn.f32x2 %0, %1, %2, %0;" : "+l"(d) : "l"(a), "l"(b));
}
__device__ __forceinline__ void unpk2(unsigned long long p, float& a, float& b) {
    asm("mov.b64 {%0, %1}, %2;" : "=f"(a), "=f"(b) : "l"(p));
}

// ---------------------------------------------------------------------------
// Non-flushing grid barrier: 32 padded counters, NBLK/32 = 4 arrivals each.
// Counters are zeroed by k_pre (block 0) before k_persist launches.
// ---------------------------------------------------------------------------
__device__ __forceinline__ void gsync(unsigned target4) {
    __syncthreads();
    if (threadIdx.x == 0) {
        asm volatile("red.release.gpu.global.add.u32 [%0], %1;"
                     :: "l"(&g_cnt[(blockIdx.x & 31) * 8]), "r"(1u) : "memory");
    }
    if (threadIdx.x < 32) {
        const unsigned* cp = &g_cnt[threadIdx.x * 8];
        unsigned v;
        while (true) {
            asm volatile("ld.acquire.gpu.global.u32 %0, [%1];" : "=r"(v) : "l"(cp) : "memory");
            if (v >= target4) break;
            __nanosleep(40);
        }
    }
    __syncthreads();
}

// ---------------------------------------------------------------------------
// Precompute GEMM (packed f32x2): 256 blocks x 1 tile.
// E-tiles load DIRECTLY from encoder tables (no staging kernel): each block
// resolves its 56 m-rows to encoder row pointers once (static schedule).
// Block 0 also zeroes the persist barrier counters.
// ---------------------------------------------------------------------------
__global__ __launch_bounds__(256)
void k_pre(const float* __restrict__ Wih,
           const float* __restrict__ b_ih, const float* __restrict__ b_hh,
           const float* __restrict__ enc_act, const float* __restrict__ enc_block) {
    extern __shared__ float2 dynp[];
    float2* Wt2 = dynp;
    float2* Es2 = dynp + PRE_W_F2;
    __shared__ const float* srow[56];

    const int t = threadIdx.x, c = t & 31, r = t >> 5;

    const int tile = blockIdx.x;
    const int nb = tile & 31, mb = (tile >> 5) & 1, kb = tile >> 6;
    const int n_base = nb * 256, m_base = mb * 56, k_base = kb * 512;

    if (tile == 0 && t < 32 * 8) g_cnt[t] = 0u;    // persist barrier counters

    // resolve encoder row pointers for this block's 56 m-rows
    if (t < 56) {
        int m = m_base + t;
        int u = 1, base = 0, cnt = 4;
        while (u < 22 && m >= base + cnt) { base += cnt; ++u; cnt = (u & 1) ? 4 : (u >> 1); }
        const float* src;
        if (m >= base + cnt) {
            src = enc_act;   // pad rows 110,111
        } else {
            int o = m - base;
            if (u & 1) src = enc_act   + ((size_t)((u - 1) >> 1) * 4        + o) * H;
            else       src = enc_block + ((size_t)((u >> 1) - 1) * (NB - 1) + o) * H;
        }
        srow[t] = src;
    }
    __syncthreads();

    unsigned long long acc[7][8];
#pragma unroll
    for (int j = 0; j < 7; j++)
#pragma unroll
        for (int i = 0; i < 8; i++) acc[j][i] = 0ull;

    float4 wst[8];
    float4 est[2];
    {
        const float4* wsrc = (const float4*)(Wih + (size_t)(n_base + t) * H + k_base);
#pragma unroll
        for (int q = 0; q < 8; q++) wst[q] = __ldcg(&wsrc[q]);
#pragma unroll
        for (int x = 0; x < 2; x++) {
            int idx = t + 256 * x;
            if (idx < 448) {
                int row = idx >> 3, q = idx & 7;
                est[x] = *(const float4*)(srow[row] + k_base + 4 * q);
            }
        }
    }

    for (int kt = 0; kt < 512; kt += 32) {
        {
            float2* wd = &Wt2[t * 17];
#pragma unroll
            for (int q = 0; q < 8; q++) {
                wd[2 * q + 0] = make_float2(wst[q].x, wst[q].y);
                wd[2 * q + 1] = make_float2(wst[q].z, wst[q].w);
            }
#pragma unroll
            for (int x = 0; x < 2; x++) {
                int idx = t + 256 * x;
                if (idx < 448) {
                    int row = idx >> 3, q = idx & 7;
                    Es2[row * 17 + 2 * q + 0] = make_float2(est[x].x, est[x].y);
                    Es2[row * 17 + 2 * q + 1] = make_float2(est[x].z, est[x].w);
                }
            }
        }
        __syncthreads();

        if (kt + 32 < 512) {
            const int k0 = k_base + kt + 32;
            const float4* wsrc = (const float4*)(Wih + (size_t)(n_base + t) * H + k0);
#pragma unroll
            for (int q = 0; q < 8; q++) wst[q] = __ldcg(&wsrc[q]);
#pragma unroll
            for (int x = 0; x < 2; x++) {
                int idx = t + 256 * x;
                if (idx < 448) {
                    int row = idx >> 3, q = idx & 7;
                    est[x] = *(const float4*)(srow[row] + k0 + 4 * q);
                }
            }
        }

#pragma unroll
        for (int kk2 = 0; kk2 < 16; kk2++) {
            unsigned long long w2[8], e2[7];
#pragma unroll
            for (int i = 0; i < 8; i++)
                w2[i] = *(const unsigned long long*)&Wt2[(c + 32 * i) * 17 + kk2];
#pragma unroll
            for (int j = 0; j < 7; j++)
                e2[j] = *(const unsigned long long*)&Es2[(r * 7 + j) * 17 + kk2];
#pragma unroll
            for (int j = 0; j < 7; j++)
#pragma unroll
                for (int i = 0; i < 8; i++)
                    fma2(acc[j][i], w2[i], e2[j]);
        }
        __syncthreads();
    }

#pragma unroll
    for (int j = 0; j < 7; j++) {
        int m = m_base + r * 7 + j;
#pragma unroll
        for (int i = 0; i < 8; i++) {
            int n = n_base + c + 32 * i;
            float lo, hi;
            unpk2(acc[j][i], lo, hi);
            float v = lo + hi;
            if (kb == 0) v += b_ih[n] + b_hh[n];
            g_pre[kb][m][n] = v;
        }
    }
}

// ---------------------------------------------------------------------------
__device__ __forceinline__ const float* dec_for(int s, const float* da,
                                                const float* db, int& ncls) {
    if (s == 0) { ncls = 4; return da; }
    if (s & 1)  { int bid = (s + 1) >> 1; ncls = bid;
                  return db + (size_t)(bid - 1) * (NB - 1) * H; }
    ncls = 4; return da + (size_t)(s >> 1) * 4 * H;
}

// quarter-summed pre value (deterministic order)
__device__ __forceinline__ float pre_sum(int row, size_t off) {
    return ((__ldcg(&g_pre[0][row][off]) + __ldcg(&g_pre[1][row][off]))
            + __ldcg(&g_pre[2][row][off])) + __ldcg(&g_pre[3][row][off]);
}

// ---------------------------------------------------------------------------
// Persistent kernel: 128 blocks x 512 threads (1/SM, 128 regs/thread).
// Block owns 16 hidden units = 64 W_hh rows. Warp w owns rows 4w..4w+3.
// k-slices: j<6 smem, j in [6,10) register-resident, j in [10,16) streamed.
// ---------------------------------------------------------------------------
__global__ __launch_bounds__(NTHR, 1)
void k_persist(const float* __restrict__ Whh,
               const float* __restrict__ b_ih, const float* __restrict__ b_hh,
               const float* __restrict__ dec_act, const float* __restrict__ dec_block,
               float* __restrict__ out, int out_size) {
    extern __shared__ float dyn[];
    float4* wc4   = (float4*)dyn;                    // [64][KC4]
    float*  scand = dyn + WC_F;                      // [2][704]
    float*  sdec  = scand + SCAND_F;                 // [114][16]
    float4* sh4   = (float4*)(dyn + SH_OFF_F);       // [512] staged h

    __shared__ float sg[64];
    __shared__ float slog[12];
    __shared__ float sunit[16];
    __shared__ float scell[16];

    const int bid = blockIdx.x, t = threadIdx.x;
    const int lane = t & 31, warp = t >> 5;
    const int j0 = bid * 16;
    const float4* W4 = (const float4*)Whh;

    const int wrow = warp * 4;
    const int gte = warp >> 2;
    const int un0 = (warp & 3) * 4;
    const float4* wp0 = W4 + (size_t)(gte * H + j0 + un0 + 0) * (H / 4);
    const float4* wp1 = W4 + (size_t)(gte * H + j0 + un0 + 1) * (H / 4);
    const float4* wp2 = W4 + (size_t)(gte * H + j0 + un0 + 2) * (H / 4);
    const float4* wp3 = W4 + (size_t)(gte * H + j0 + un0 + 3) * (H / 4);

    // ---- startup loads ----
    for (int idx = t; idx < 64 * KC4; idx += NTHR) {
        int R = idx / KC4, q = idx - R * KC4;
        size_t grow = (size_t)((R >> 4) * H + j0 + (R & 15));
        wc4[R * KC4 + q] = __ldcg(&W4[grow * (H / 4) + q]);
    }
    for (int e = t; e < SDEC_F; e += NTHR) {
        int cr = e >> 4, u = e & 15;
        int off = 0, nc = 0;
        const float* dp = dec_act;
        for (int s = 0; s <= 22; s++) {
            dp = dec_for(s, dec_act, dec_block, nc);
            if (cr < off + nc) break;
            off += nc;
        }
        int cls = cr - off;
        sdec[e] = __ldcg(&dp[(size_t)cls * H + j0 + u]);
    }
    for (int idx = t; idx < 4 * 64; idx += NTHR) {   // step-1 candidates, buf 1
        int cd = idx >> 6, c = idx & 63;
        size_t off = (size_t)(c >> 4) * H + j0 + (c & 15);
        scand[704 + idx] = pre_sum(cd, off);
    }

    // register-resident W slice: rows wrow..wrow+3, j = JR0..JR1-1
    float4 wr0[JR1 - JR0], wr1[JR1 - JR0], wr2[JR1 - JR0], wr3[JR1 - JR0];
#pragma unroll
    for (int jj = 0; jj < JR1 - JR0; jj++) {
        const int idx = lane + 32 * (JR0 + jj);
        wr0[jj] = __ldcg(&wp0[idx]);
        wr1[jj] = __ldcg(&wp1[idx]);
        wr2[jj] = __ldcg(&wp2[idx]);
        wr3[jj] = __ldcg(&wp3[idx]);
    }

    // ---- step 0: gates = biases ----
    if (t < 16) {
        int j = j0 + t;
        float gi = b_ih[j        ] + b_hh[j        ];
        float gg = b_ih[2 * H + j] + b_hh[2 * H + j];
        float go = b_ih[3 * H + j] + b_hh[3 * H + j];
        float c2 = sigmoidf_(gi) * tanhf(gg);
        float h2 = sigmoidf_(go) * tanhf(c2);
        scell[t] = c2;
        sunit[t] = h2;
        __stcg(&g_h[0][j], h2);
    }
    __syncthreads();
    if (warp < 4) {
        float v = (lane < 16) ? sunit[lane] * sdec[warp * 16 + lane] : 0.0f;
        v += __shfl_down_sync(0xffffffffu, v, 8);
        v += __shfl_down_sync(0xffffffffu, v, 4);
        v += __shfl_down_sync(0xffffffffu, v, 2);
        v += __shfl_down_sync(0xffffffffu, v, 1);
        if (lane == 0) __stcg(&g_part[1][warp][bid], v);
    }

    unsigned phase = 1;
    gsync(phase * 4);

    // ---- 22 fused steps ----
    int cand_base = 0, ncand = 4, doff = 4;
    for (int s = 1; s <= 22; s++) {
        const int parity = s & 1, pr = s & 1, pw = (s + 1) & 1;

        // stage h into smem
        sh4[t] = __ldcg(&((const float4*)g_h[parity ^ 1])[t]);

        // prologue: per-class sums of 128 block-partials
        if (warp < ncand) {
            const float* p = g_part[pr][warp];
            float a = __ldcg(&p[lane]) + __ldcg(&p[lane + 32])
                    + __ldcg(&p[lane + 64]) + __ldcg(&p[lane + 96]);
            a += __shfl_down_sync(0xffffffffu, a, 16);
            a += __shfl_down_sync(0xffffffffu, a, 8);
            a += __shfl_down_sync(0xffffffffu, a, 4);
            a += __shfl_down_sync(0xffffffffu, a, 2);
            a += __shfl_down_sync(0xffffffffu, a, 1);
            if (lane == 0) slog[warp] = a;
        }
        __syncthreads();

        // GEMV: warp computes rows wrow..wrow+3 fully
        float a0 = 0.f, a1 = 0.f, a2 = 0.f, a3 = 0.f;

        // streamed region (j = JS0..15)
#pragma unroll
        for (int j = JS0; j < 16; j++) {
            const int idx = lane + 32 * j;
            float4 w0 = __ldcg(&wp0[idx]);
            float4 w1 = __ldcg(&wp1[idx]);
            float4 w2 = __ldcg(&wp2[idx]);
            float4 w3 = __ldcg(&wp3[idx]);
            float4 hv = sh4[idx];
            a0 += hv.x * w0.x + hv.y * w0.y + hv.z * w0.z + hv.w * w0.w;
            a1 += hv.x * w1.x + hv.y * w1.y + hv.z * w1.z + hv.w * w1.w;
            a2 += hv.x * w2.x + hv.y * w2.y + hv.z * w2.z + hv.w * w2.w;
            a3 += hv.x * w3.x + hv.y * w3.y + hv.z * w3.z + hv.w * w3.w;
        }
        // register-resident region (j = JR0..JR1-1)
#pragma unroll
        for (int jj = 0; jj < JR1 - JR0; jj++) {
            const int idx = lane + 32 * (JR0 + jj);
            float4 hv = sh4[idx];
            a0 += hv.x * wr0[jj].x + hv.y * wr0[jj].y + hv.z * wr0[jj].z + hv.w * wr0[jj].w;
            a1 += hv.x * wr1[jj].x + hv.y * wr1[jj].y + hv.z * wr1[jj].z + hv.w * wr1[jj].w;
            a2 += hv.x * wr2[jj].x + hv.y * wr2[jj].y + hv.z * wr2[jj].z + hv.w * wr2[jj].w;
            a3 += hv.x * wr3[jj].x + hv.y * wr3[jj].y + hv.z * wr3[jj].z + hv.w * wr3[jj].w;
        }
        // smem-cached region (j = 0..5)
#pragma unroll
        for (int j = 0; j < 6; j++) {
            const int idx = lane + 32 * j;
            float4 hv = sh4[idx];
            float4 w0 = wc4[(wrow + 0) * KC4 + idx];
            float4 w1 = wc4[(wrow + 1) * KC4 + idx];
            float4 w2 = wc4[(wrow + 2) * KC4 + idx];
            float4 w3 = wc4[(wrow + 3) * KC4 + idx];
            a0 += hv.x * w0.x + hv.y * w0.y + hv.z * w0.z + hv.w * w0.w;
            a1 += hv.x * w1.x + hv.y * w1.y + hv.z * w1.z + hv.w * w1.w;
            a2 += hv.x * w2.x + hv.y * w2.y + hv.z * w2.z + hv.w * w2.w;
            a3 += hv.x * w3.x + hv.y * w3.y + hv.z * w3.z + hv.w * w3.w;
        }

#pragma unroll
        for (int o = 16; o > 0; o >>= 1) {
            a0 += __shfl_down_sync(0xffffffffu, a0, o);
            a1 += __shfl_down_sync(0xffffffffu, a1, o);
            a2 += __shfl_down_sync(0xffffffffu, a2, o);
            a3 += __shfl_down_sync(0xffffffffu, a3, o);
        }
        if (lane == 0) {
            sg[wrow + 0] = a0; sg[wrow + 1] = a1;
            sg[wrow + 2] = a2; sg[wrow + 3] = a3;
        }
        __syncthreads();

        // tail: 16 threads do argmax + gate math (pure smem)
        if (t < 16) {
            int lc = 0;
            {
                float bv = slog[0];
                for (int cc = 1; cc < ncand; cc++)
                    if (slog[cc] > bv) { bv = slog[cc]; lc = cc; }
            }
            const float* cp = scand + (s & 1) * 704 + lc * 64;
            float gi = sg[t]      + cp[t];
            float gf = sg[16 + t] + cp[16 + t];
            float gg = sg[32 + t] + cp[32 + t];
            float go = sg[48 + t] + cp[48 + t];
            float c2 = sigmoidf_(gf) * scell[t] + sigmoidf_(gi) * tanhf(gg);
            float h2 = sigmoidf_(go) * tanhf(c2);
            scell[t] = c2;
            sunit[t] = h2;
            __stcg(&g_h[parity][j0 + t], h2);
            if (s == 22) __stcg(&g_c[j0 + t], c2);
        }
        __syncthreads();

        // epilogue: decode partials from smem decoder rows
        int ncls;
        dec_for(s, dec_act, dec_block, ncls);
        if (warp < ncls) {
            float v = (lane < 16) ? sunit[lane] * sdec[(doff + warp) * 16 + lane] : 0.0f;
            v += __shfl_down_sync(0xffffffffu, v, 8);
            v += __shfl_down_sync(0xffffffffu, v, 4);
            v += __shfl_down_sync(0xffffffffu, v, 2);
            v += __shfl_down_sync(0xffffffffu, v, 1);
            if (lane == 0) __stcg(&g_part[pw][warp][bid], v);
        }

        // prefetch + quarter-sum next step's candidate rows (overlaps barrier)
        int nb_next = cand_base + ncand;
        if (s < 22) {
            float* dstb = scand + ((s + 1) & 1) * 704;
            for (int idx = t; idx < ncls * 64; idx += NTHR) {
                int cd = idx >> 6, c = idx & 63;
                size_t off = (size_t)(c >> 4) * H + j0 + (c & 15);
                dstb[idx] = pre_sum(nb_next + cd, off);
            }
        }

        cand_base = nb_next;
        ncand = ncls;
        doff += ncls;

        ++phase;
        gsync(phase * 4);
    }

    // ---- final argmax ----
    if (warp < 4) {
        const float* p = g_part[1][warp];
        float a = __ldcg(&p[lane]) + __ldcg(&p[lane + 32])
                + __ldcg(&p[lane + 64]) + __ldcg(&p[lane + 96]);
        a += __shfl_down_sync(0xffffffffu, a, 16);
        a += __shfl_down_sync(0xffffffffu, a, 8);
        a += __shfl_down_sync(0xffffffffu, a, 4);
        a += __shfl_down_sync(0xffffffffu, a, 2);
        a += __shfl_down_sync(0xffffffffu, a, 1);
        if (lane == 0) slog[warp] = a;
    }
    __syncthreads();

    int best = 0;
    {
        float bv = slog[0];
        for (int cc = 1; cc < 4; cc++)
            if (slog[cc] > bv) { bv = slog[cc]; best = cc; }
    }

    // ---- stage final h, c into smem (reuse wc4 region), then float4 output ----
    float* hbuf = dyn;
    float* cbuf = dyn + 2048;
    {
        float4* hb4 = (float4*)hbuf;
        float4* cb4 = (float4*)cbuf;
        hb4[t] = __ldcg(&((const float4*)g_h[0])[t]);
        cb4[t] = __ldcg(&((const float4*)g_c)[t]);
    }
    __syncthreads();

    const float fidx = (float)best;
    const long HB = (long)B * H;
    const long n4 = out_size >> 2;
    float4* out4 = (float4*)out;
    for (long i4 = (long)bid * NTHR + t; i4 < n4; i4 += (long)NBLK * NTHR) {
        long i = i4 << 2;
        float4 v;
        if (i < B) {
            v = make_float4(fidx, fidx, fidx, fidx);
        } else if (i < B + HB) {
            v = *(const float4*)&hbuf[(i - B) & (H - 1)];
        } else {
            v = *(const float4*)&cbuf[(i - B - HB) & (H - 1)];
        }
        __stcs(&out4[i4], v);
    }
    for (long i = (n4 << 2) + (long)bid * NTHR + t; i < out_size; i += (long)NBLK * NTHR) {
        float v;
        if (i < B)               v = fidx;
        else if (i < B + HB)     v = hbuf[(i - B) & (H - 1)];
        else if (i < B + 2 * HB) v = cbuf[(i - B - HB) & (H - 1)];
        else                     v = 0.0f;
        __stcs(out + i, v);
    }
}

// ---------------------------------------------------------------------------
extern "C" void kernel_launch(void* const* d_in, const int* in_sizes, int n_in,
                              void* d_out, int out_size) {
    (void)in_sizes; (void)n_in;
    const float* Wih       = (const float*)d_in[1];
    const float* Whh       = (const float*)d_in[2];
    const float* b_ih      = (const float*)d_in[3];
    const float* b_hh      = (const float*)d_in[4];
    const float* enc_act   = (const float*)d_in[5];
    const float* enc_block = (const float*)d_in[6];
    const float* dec_act   = (const float*)d_in[7];
    const float* dec_block = (const float*)d_in[8];

    static int attr_done = 0;
    if (!attr_done) {
        cudaFuncSetAttribute(k_persist, cudaFuncAttributeMaxDynamicSharedMemorySize, P_DSMEM);
        cudaFuncSetAttribute(k_pre, cudaFuncAttributeMaxDynamicSharedMemorySize, PRE_DSMEM);
        attr_done = 1;
    }

    k_pre<<<256, 256, PRE_DSMEM>>>(Wih, b_ih, b_hh, enc_act, enc_block);
    k_persist<<<NBLK, NTHR, P_DSMEM>>>(Whh, b_ih, b_hh, dec_act, dec_block,
                                       (float*)d_out, out_size);
}

// round 14
// speedup vs baseline: 1.0266x; 1.0266x over previous
#include <cuda_runtime.h>
#include <cstddef>
#include <cstdint>

#define H     2048
#define B     1024
#define NB    12
#define NROW  112
#define GATES 8192
#define NBLK  128                 // persistent blocks (1/SM)
#define NTHR  512
#define KC4   192                 // float4 k-prefix of each W_hh row in smem (j<6)
#define JR0   6                   // register-resident j range [JR0, JR1)
#define JR1   10
#define JS0   10                  // streamed j range [JS0, 16)

// persist dynamic smem layout (floats)
#define WC_F      (64 * KC4 * 4)          // 49152
#define STAGE_F   (4 * 704)               // 2816 : 4 k-quarters x 11 cands x 64
#define SDEC_F    (114 * 16)              // 1824
#define SH_OFF_F  (WC_F + STAGE_F + SDEC_F)
#define P_DSMEM   ((SH_OFF_F + 2048) * 4) // 223360 B

// k_pre dynamic smem: pitch-18 float2 tiles (16B-aligned pairs, conflict-free LDS.128)
#define PP         18
#define PRE_W_F2   (256 * PP)
#define PRE_E_F2   (56 * PP)
#define PRE_DSMEM  ((PRE_W_F2 + PRE_E_F2) * 8)   // 44928 B

// ---------------------------------------------------------------------------
__device__ __align__(16) float g_h[2][H];
__device__ __align__(16) float g_c[H];
__device__ __align__(16) float g_pre[4][NROW][GATES];   // k-quarter partials
__device__ float g_part[2][12][NBLK];
__device__ unsigned g_cnt[32 * 8];

__device__ __forceinline__ float sigmoidf_(float v) { return 1.0f / (1.0f + expf(-v)); }

__device__ __forceinline__ void fma2(unsigned long long& d,
                                     unsigned long long a, unsigned long long b) {
    asm("fma.rn.f32x2 %0, %1, %2, %0;" : "+l"(d) : "l"(a), "l"(b));
}
__device__ __forceinline__ void unpk2(unsigned long long p, float& a, float& b) {
    asm("mov.b64 {%0, %1}, %2;" : "=f"(a), "=f"(b) : "l"(p));
}
__device__ __forceinline__ void lds128_2ull(unsigned long long& a, unsigned long long& b,
                                            const void* p) {
    uint32_t addr = (uint32_t)__cvta_generic_to_shared(p);
    asm("ld.shared.v2.u64 {%0, %1}, [%2];" : "=l"(a), "=l"(b) : "r"(addr));
}
__device__ __forceinline__ void cpasync16(const float* smem_dst, const float* gsrc) {
    uint32_t d = (uint32_t)__cvta_generic_to_shared(smem_dst);
    asm volatile("cp.async.cg.shared.global [%0], [%1], 16;" :: "r"(d), "l"(gsrc));
}

// ---------------------------------------------------------------------------
// Non-flushing grid barrier: 32 padded counters, NBLK/32 = 4 arrivals each.
// Counters zeroed by k_pre block 0.
// ---------------------------------------------------------------------------
__device__ __forceinline__ void gsync(unsigned target4) {
    __syncthreads();
    if (threadIdx.x == 0) {
        asm volatile("red.release.gpu.global.add.u32 [%0], %1;"
                     :: "l"(&g_cnt[(blockIdx.x & 31) * 8]), "r"(1u) : "memory");
    }
    if (threadIdx.x < 32) {
        const unsigned* cp = &g_cnt[threadIdx.x * 8];
        unsigned v;
        while (true) {
            asm volatile("ld.acquire.gpu.global.u32 %0, [%1];" : "=r"(v) : "l"(cp) : "memory");
            if (v >= target4) break;
            __nanosleep(40);
        }
    }
    __syncthreads();
}

// ---------------------------------------------------------------------------
// Precompute GEMM (packed f32x2, LDS.128 inner loop): 256 blocks x 1 tile.
// E-tiles load directly from encoder tables (static row map). Block 0 zeroes
// the persist barrier counters.
// ---------------------------------------------------------------------------
__global__ __launch_bounds__(256)
void k_pre(const float* __restrict__ Wih,
           const float* __restrict__ b_ih, const float* __restrict__ b_hh,
           const float* __restrict__ enc_act, const float* __restrict__ enc_block) {
    extern __shared__ float2 dynp[];
    float2* Wt2 = dynp;                   // [256][PP]
    float2* Es2 = dynp + PRE_W_F2;        // [56][PP]
    __shared__ const float* srow[56];

    const int t = threadIdx.x, c = t & 31, r = t >> 5;

    const int tile = blockIdx.x;
    const int nb = tile & 31, mb = (tile >> 5) & 1, kb = tile >> 6;
    const int n_base = nb * 256, m_base = mb * 56, k_base = kb * 512;

    if (tile == 0 && t < 32 * 8) g_cnt[t] = 0u;

    if (t < 56) {
        int m = m_base + t;
        int u = 1, base = 0, cnt = 4;
        while (u < 22 && m >= base + cnt) { base += cnt; ++u; cnt = (u & 1) ? 4 : (u >> 1); }
        const float* src;
        if (m >= base + cnt) {
            src = enc_act;   // pad rows 110,111
        } else {
            int o = m - base;
            if (u & 1) src = enc_act   + ((size_t)((u - 1) >> 1) * 4        + o) * H;
            else       src = enc_block + ((size_t)((u >> 1) - 1) * (NB - 1) + o) * H;
        }
        srow[t] = src;
    }
    __syncthreads();

    unsigned long long acc[7][8];
#pragma unroll
    for (int j = 0; j < 7; j++)
#pragma unroll
        for (int i = 0; i < 8; i++) acc[j][i] = 0ull;

    float4 wst[8];
    float4 est[2];
    {
        const float4* wsrc = (const float4*)(Wih + (size_t)(n_base + t) * H + k_base);
#pragma unroll
        for (int q = 0; q < 8; q++) wst[q] = __ldcg(&wsrc[q]);
#pragma unroll
        for (int x = 0; x < 2; x++) {
            int idx = t + 256 * x;
            if (idx < 448) {
                int row = idx >> 3, q = idx & 7;
                est[x] = __ldcg((const float4*)(srow[row] + k_base + 4 * q));
            }
        }
    }

    for (int kt = 0; kt < 512; kt += 32) {
        {
            float2* wd = &Wt2[t * PP];
#pragma unroll
            for (int q = 0; q < 8; q++) {
                wd[2 * q + 0] = make_float2(wst[q].x, wst[q].y);
                wd[2 * q + 1] = make_float2(wst[q].z, wst[q].w);
            }
#pragma unroll
            for (int x = 0; x < 2; x++) {
                int idx = t + 256 * x;
                if (idx < 448) {
                    int row = idx >> 3, q = idx & 7;
                    Es2[row * PP + 2 * q + 0] = make_float2(est[x].x, est[x].y);
                    Es2[row * PP + 2 * q + 1] = make_float2(est[x].z, est[x].w);
                }
            }
        }
        __syncthreads();

        if (kt + 32 < 512) {
            const int k0 = k_base + kt + 32;
            const float4* wsrc = (const float4*)(Wih + (size_t)(n_base + t) * H + k0);
#pragma unroll
            for (int q = 0; q < 8; q++) wst[q] = __ldcg(&wsrc[q]);
#pragma unroll
            for (int x = 0; x < 2; x++) {
                int idx = t + 256 * x;
                if (idx < 448) {
                    int row = idx >> 3, q = idx & 7;
                    est[x] = __ldcg((const float4*)(srow[row] + k0 + 4 * q));
                }
            }
        }

        // compute: two kk2 slices per LDS.128
#pragma unroll
        for (int kk2 = 0; kk2 < 16; kk2 += 2) {
            unsigned long long wa[8], wb[8], ea[7], eb[7];
#pragma unroll
            for (int i = 0; i < 8; i++)
                lds128_2ull(wa[i], wb[i], &Wt2[(c + 32 * i) * PP + kk2]);
#pragma unroll
            for (int j = 0; j < 7; j++)
                lds128_2ull(ea[j], eb[j], &Es2[(r * 7 + j) * PP + kk2]);
#pragma unroll
            for (int j = 0; j < 7; j++)
#pragma unroll
                for (int i = 0; i < 8; i++)
                    fma2(acc[j][i], wa[i], ea[j]);
#pragma unroll
            for (int j = 0; j < 7; j++)
#pragma unroll
                for (int i = 0; i < 8; i++)
                    fma2(acc[j][i], wb[i], eb[j]);
        }
        __syncthreads();
    }

#pragma unroll
    for (int j = 0; j < 7; j++) {
        int m = m_base + r * 7 + j;
#pragma unroll
        for (int i = 0; i < 8; i++) {
            int n = n_base + c + 32 * i;
            float lo, hi;
            unpk2(acc[j][i], lo, hi);
            float v = lo + hi;
            if (kb == 0) v += b_ih[n] + b_hh[n];
            g_pre[kb][m][n] = v;
        }
    }
}

// ---------------------------------------------------------------------------
__device__ __forceinline__ const float* dec_for(int s, const float* da,
                                                const float* db, int& ncls) {
    if (s == 0) { ncls = 4; return da; }
    if (s & 1)  { int bid = (s + 1) >> 1; ncls = bid;
                  return db + (size_t)(bid - 1) * (NB - 1) * H; }
    ncls = 4; return da + (size_t)(s >> 1) * 4 * H;
}

// ---------------------------------------------------------------------------
// Persistent kernel: 128 blocks x 512 threads (1/SM, 128 regs/thread).
// Candidate pre-rows prefetched via cp.async as RAW 4 quarters into a single
// staging buffer; the 16-thread tail sums quarters (deterministic order).
// ---------------------------------------------------------------------------
__global__ __launch_bounds__(NTHR, 1)
void k_persist(const float* __restrict__ Whh,
               const float* __restrict__ b_ih, const float* __restrict__ b_hh,
               const float* __restrict__ dec_act, const float* __restrict__ dec_block,
               float* __restrict__ out, int out_size) {
    extern __shared__ float dyn[];
    float4* wc4   = (float4*)dyn;                    // [64][KC4]
    float*  stage = dyn + WC_F;                      // [4][704]
    float*  sdec  = stage + STAGE_F;                 // [114][16]
    float4* sh4   = (float4*)(dyn + SH_OFF_F);       // [512] staged h

    __shared__ float sg[64];
    __shared__ float slog[12];
    __shared__ float sunit[16];
    __shared__ float scell[16];

    const int bid = blockIdx.x, t = threadIdx.x;
    const int lane = t & 31, warp = t >> 5;
    const int j0 = bid * 16;
    const float4* W4 = (const float4*)Whh;

    const int wrow = warp * 4;
    const int gte = warp >> 2;
    const int un0 = (warp & 3) * 4;
    const float4* wp0 = W4 + (size_t)(gte * H + j0 + un0 + 0) * (H / 4);
    const float4* wp1 = W4 + (size_t)(gte * H + j0 + un0 + 1) * (H / 4);
    const float4* wp2 = W4 + (size_t)(gte * H + j0 + un0 + 2) * (H / 4);
    const float4* wp3 = W4 + (size_t)(gte * H + j0 + un0 + 3) * (H / 4);

    // ---- startup loads ----
    for (int idx = t; idx < 64 * KC4; idx += NTHR) {
        int R = idx / KC4, q = idx - R * KC4;
        size_t grow = (size_t)((R >> 4) * H + j0 + (R & 15));
        wc4[R * KC4 + q] = __ldcg(&W4[grow * (H / 4) + q]);
    }
    for (int e = t; e < SDEC_F; e += NTHR) {
        int cr = e >> 4, u = e & 15;
        int off = 0, nc = 0;
        const float* dp = dec_act;
        for (int s = 0; s <= 22; s++) {
            dp = dec_for(s, dec_act, dec_block, nc);
            if (cr < off + nc) break;
            off += nc;
        }
        int cls = cr - off;
        sdec[e] = __ldcg(&dp[(size_t)cls * H + j0 + u]);
    }
    // step-1 candidates: raw quarters into stage
    for (int idx = t; idx < 4 * 4 * 64; idx += NTHR) {
        int q = idx >> 8, rem = idx & 255;
        int cd = rem >> 6, c = rem & 63;
        stage[q * 704 + cd * 64 + c] =
            __ldcg(&g_pre[q][cd][(size_t)(c >> 4) * H + j0 + (c & 15)]);
    }

    // register-resident W slice: rows wrow..wrow+3, j = JR0..JR1-1
    float4 wr0[JR1 - JR0], wr1[JR1 - JR0], wr2[JR1 - JR0], wr3[JR1 - JR0];
#pragma unroll
    for (int jj = 0; jj < JR1 - JR0; jj++) {
        const int idx = lane + 32 * (JR0 + jj);
        wr0[jj] = __ldcg(&wp0[idx]);
        wr1[jj] = __ldcg(&wp1[idx]);
        wr2[jj] = __ldcg(&wp2[idx]);
        wr3[jj] = __ldcg(&wp3[idx]);
    }

    // ---- step 0: gates = biases ----
    if (t < 16) {
        int j = j0 + t;
        float gi = b_ih[j        ] + b_hh[j        ];
        float gg = b_ih[2 * H + j] + b_hh[2 * H + j];
        float go = b_ih[3 * H + j] + b_hh[3 * H + j];
        float c2 = sigmoidf_(gi) * tanhf(gg);
        float h2 = sigmoidf_(go) * tanhf(c2);
        scell[t] = c2;
        sunit[t] = h2;
        __stcg(&g_h[0][j], h2);
    }
    __syncthreads();
    if (warp < 4) {
        float v = (lane < 16) ? sunit[lane] * sdec[warp * 16 + lane] : 0.0f;
        v += __shfl_down_sync(0xffffffffu, v, 8);
        v += __shfl_down_sync(0xffffffffu, v, 4);
        v += __shfl_down_sync(0xffffffffu, v, 2);
        v += __shfl_down_sync(0xffffffffu, v, 1);
        if (lane == 0) __stcg(&g_part[1][warp][bid], v);
    }

    unsigned phase = 1;
    gsync(phase * 4);

    // ---- 22 fused steps ----
    int cand_base = 0, ncand = 4, doff = 4;
    for (int s = 1; s <= 22; s++) {
        const int parity = s & 1, pr = s & 1, pw = (s + 1) & 1;

        // stage h into smem
        sh4[t] = __ldcg(&((const float4*)g_h[parity ^ 1])[t]);

        // prologue: per-class sums of 128 block-partials
        if (warp < ncand) {
            const float* p = g_part[pr][warp];
            float a = __ldcg(&p[lane]) + __ldcg(&p[lane + 32])
                    + __ldcg(&p[lane + 64]) + __ldcg(&p[lane + 96]);
            a += __shfl_down_sync(0xffffffffu, a, 16);
            a += __shfl_down_sync(0xffffffffu, a, 8);
            a += __shfl_down_sync(0xffffffffu, a, 4);
            a += __shfl_down_sync(0xffffffffu, a, 2);
            a += __shfl_down_sync(0xffffffffu, a, 1);
            if (lane == 0) slog[warp] = a;
        }
        __syncthreads();

        // GEMV: warp computes rows wrow..wrow+3 fully
        float a0 = 0.f, a1 = 0.f, a2 = 0.f, a3 = 0.f;

        // streamed region (j = JS0..15)
#pragma unroll
        for (int j = JS0; j < 16; j++) {
            const int idx = lane + 32 * j;
            float4 w0 = __ldcg(&wp0[idx]);
            float4 w1 = __ldcg(&wp1[idx]);
            float4 w2 = __ldcg(&wp2[idx]);
            float4 w3 = __ldcg(&wp3[idx]);
            float4 hv = sh4[idx];
            a0 += hv.x * w0.x + hv.y * w0.y + hv.z * w0.z + hv.w * w0.w;
            a1 += hv.x * w1.x + hv.y * w1.y + hv.z * w1.z + hv.w * w1.w;
            a2 += hv.x * w2.x + hv.y * w2.y + hv.z * w2.z + hv.w * w2.w;
            a3 += hv.x * w3.x + hv.y * w3.y + hv.z * w3.z + hv.w * w3.w;
        }
        // register-resident region (j = JR0..JR1-1)
#pragma unroll
        for (int jj = 0; jj < JR1 - JR0; jj++) {
            const int idx = lane + 32 * (JR0 + jj);
            float4 hv = sh4[idx];
            a0 += hv.x * wr0[jj].x + hv.y * wr0[jj].y + hv.z * wr0[jj].z + hv.w * wr0[jj].w;
            a1 += hv.x * wr1[jj].x + hv.y * wr1[jj].y + hv.z * wr1[jj].z + hv.w * wr1[jj].w;
            a2 += hv.x * wr2[jj].x + hv.y * wr2[jj].y + hv.z * wr2[jj].z + hv.w * wr2[jj].w;
            a3 += hv.x * wr3[jj].x + hv.y * wr3[jj].y + hv.z * wr3[jj].z + hv.w * wr3[jj].w;
        }
        // smem-cached region (j = 0..5)
#pragma unroll
        for (int j = 0; j < 6; j++) {
            const int idx = lane + 32 * j;
            float4 hv = sh4[idx];
            float4 w0 = wc4[(wrow + 0) * KC4 + idx];
            float4 w1 = wc4[(wrow + 1) * KC4 + idx];
            float4 w2 = wc4[(wrow + 2) * KC4 + idx];
            float4 w3 = wc4[(wrow + 3) * KC4 + idx];
            a0 += hv.x * w0.x + hv.y * w0.y + hv.z * w0.z + hv.w * w0.w;
            a1 += hv.x * w1.x + hv.y * w1.y + hv.z * w1.z + hv.w * w1.w;
            a2 += hv.x * w2.x + hv.y * w2.y + hv.z * w2.z + hv.w * w2.w;
            a3 += hv.x * w3.x + hv.y * w3.y + hv.z * w3.z + hv.w * w3.w;
        }

#pragma unroll
        for (int o = 16; o > 0; o >>= 1) {
            a0 += __shfl_down_sync(0xffffffffu, a0, o);
            a1 += __shfl_down_sync(0xffffffffu, a1, o);
            a2 += __shfl_down_sync(0xffffffffu, a2, o);
            a3 += __shfl_down_sync(0xffffffffu, a3, o);
        }
        if (lane == 0) {
            sg[wrow + 0] = a0; sg[wrow + 1] = a1;
            sg[wrow + 2] = a2; sg[wrow + 3] = a3;
        }
        asm volatile("cp.async.wait_group 0;" ::: "memory");
        __syncthreads();

        // tail: 16 threads do argmax + quarter-sum + gate math (pure smem)
        if (t < 16) {
            int lc = 0;
            {
                float bv = slog[0];
                for (int cc = 1; cc < ncand; cc++)
                    if (slog[cc] > bv) { bv = slog[cc]; lc = cc; }
            }
            const float* cp = stage + lc * 64;
            float pi = ((cp[t]      + cp[704 + t])      + cp[1408 + t])      + cp[2112 + t];
            float pf = ((cp[16 + t] + cp[704 + 16 + t]) + cp[1408 + 16 + t]) + cp[2112 + 16 + t];
            float pg = ((cp[32 + t] + cp[704 + 32 + t]) + cp[1408 + 32 + t]) + cp[2112 + 32 + t];
            float po = ((cp[48 + t] + cp[704 + 48 + t]) + cp[1408 + 48 + t]) + cp[2112 + 48 + t];
            float gi = sg[t]      + pi;
            float gf = sg[16 + t] + pf;
            float gg = sg[32 + t] + pg;
            float go = sg[48 + t] + po;
            float c2 = sigmoidf_(gf) * scell[t] + sigmoidf_(gi) * tanhf(gg);
            float h2 = sigmoidf_(go) * tanhf(c2);
            scell[t] = c2;
            sunit[t] = h2;
            __stcg(&g_h[parity][j0 + t], h2);
            if (s == 22) __stcg(&g_c[j0 + t], c2);
        }
        __syncthreads();   // tail reads of stage complete before cp.async overwrite

        // epilogue: decode partials from smem decoder rows
        int ncls;
        dec_for(s, dec_act, dec_block, ncls);
        if (warp < ncls) {
            float v = (lane < 16) ? sunit[lane] * sdec[(doff + warp) * 16 + lane] : 0.0f;
            v += __shfl_down_sync(0xffffffffu, v, 8);
            v += __shfl_down_sync(0xffffffffu, v, 4);
            v += __shfl_down_sync(0xffffffffu, v, 2);
            v += __shfl_down_sync(0xffffffffu, v, 1);
            if (lane == 0) __stcg(&g_part[pw][warp][bid], v);
        }

        // cp.async prefetch of next step's candidate quarters (register-free)
        int nb_next = cand_base + ncand;
        if (s < 22) {
            int chunks = ncls * 64;               // (cd,c4) x 4 quarters
            for (int ch = t; ch < chunks; ch += NTHR) {
                int q = ch & 3, rest = ch >> 2;
                int cd = rest >> 4, c4 = rest & 15;
                int g = c4 >> 2, qf = c4 & 3;
                cpasync16(stage + q * 704 + cd * 64 + g * 16 + qf * 4,
                          &g_pre[q][nb_next + cd][(size_t)g * H + j0 + qf * 4]);
            }
        }
        asm volatile("cp.async.commit_group;" ::: "memory");

        cand_base = nb_next;
        ncand = ncls;
        doff += ncls;

        ++phase;
        gsync(phase * 4);
    }

    // ---- final argmax ----
    if (warp < 4) {
        const float* p = g_part[1][warp];
        float a = __ldcg(&p[lane]) + __ldcg(&p[lane + 32])
                + __ldcg(&p[lane + 64]) + __ldcg(&p[lane + 96]);
        a += __shfl_down_sync(0xffffffffu, a, 16);
        a += __shfl_down_sync(0xffffffffu, a, 8);
        a += __shfl_down_sync(0xffffffffu, a, 4);
        a += __shfl_down_sync(0xffffffffu, a, 2);
        a += __shfl_down_sync(0xffffffffu, a, 1);
        if (lane == 0) slog[warp] = a;
    }
    __syncthreads();

    int best = 0;
    {
        float bv = slog[0];
        for (int cc = 1; cc < 4; cc++)
            if (slog[cc] > bv) { bv = slog[cc]; best = cc; }
    }

    // ---- stage final h, c into smem, then float4 output broadcast ----
    float* hbuf = dyn;
    float* cbuf = dyn + 2048;
    {
        float4* hb4 = (float4*)hbuf;
        float4* cb4 = (float4*)cbuf;
        hb4[t] = __ldcg(&((const float4*)g_h[0])[t]);
        cb4[t] = __ldcg(&((const float4*)g_c)[t]);
    }
    __syncthreads();

    const float fidx = (float)best;
    const long HB = (long)B * H;
    const long n4 = out_size >> 2;
    float4* out4 = (float4*)out;
    for (long i4 = (long)bid * NTHR + t; i4 < n4; i4 += (long)NBLK * NTHR) {
        long i = i4 << 2;
        float4 v;
        if (i < B) {
            v = make_float4(fidx, fidx, fidx, fidx);
        } else if (i < B + HB) {
            v = *(const float4*)&hbuf[(i - B) & (H - 1)];
        } else {
            v = *(const float4*)&cbuf[(i - B - HB) & (H - 1)];
        }
        __stcs(&out4[i4], v);
    }
    for (long i = (n4 << 2) + (long)bid * NTHR + t; i < out_size; i += (long)NBLK * NTHR) {
        float v;
        if (i < B)               v = fidx;
        else if (i < B + HB)     v = hbuf[(i - B) & (H - 1)];
        else if (i < B + 2 * HB) v = cbuf[(i - B - HB) & (H - 1)];
        else                     v = 0.0f;
        __stcs(out + i, v);
    }
}

// ---------------------------------------------------------------------------
extern "C" void kernel_launch(void* const* d_in, const int* in_sizes, int n_in,
                              void* d_out, int out_size) {
    (void)in_sizes; (void)n_in;
    const float* Wih       = (const float*)d_in[1];
    const float* Whh       = (const float*)d_in[2];
    const float* b_ih      = (const float*)d_in[3];
    const float* b_hh      = (const float*)d_in[4];
    const float* enc_act   = (const float*)d_in[5];
    const float* enc_block = (const float*)d_in[6];
    const float* dec_act   = (const float*)d_in[7];
    const float* dec_block = (const float*)d_in[8];

    static int attr_done = 0;
    if (!attr_done) {
        cudaFuncSetAttribute(k_persist, cudaFuncAttributeMaxDynamicSharedMemorySize, P_DSMEM);
        cudaFuncSetAttribute(k_pre, cudaFuncAttributeMaxDynamicSharedMemorySize, PRE_DSMEM);
        attr_done = 1;
    }

    k_pre<<<256, 256, PRE_DSMEM>>>(Wih, b_ih, b_hh, enc_act, enc_block);
    k_persist<<<NBLK, NTHR, P_DSMEM>>>(Whh, b_ih, b_hh, dec_act, dec_block,
                                       (float*)d_out, out_size);
}

// round 15
// speedup vs baseline: 1.0765x; 1.0486x over previous
#include <cuda_runtime.h>
#include <cstddef>
#include <cstdint>

#define H     2048
#define B     1024
#define NB    12
#define NROW  112
#define GATES 8192
#define NBLK  128                 // persistent blocks (1/SM)
#define NTHR  512
#define KC4   192                 // float4 k-prefix of each W_hh row in smem (j<6)
#define JR0   6                   // register-resident j range [JR0, JR1)
#define JR1   10
#define JS0   10                  // streamed j range [JS0, 16)

// persist dynamic smem layout (floats)
#define WC_F      (64 * KC4 * 4)          // 49152
#define STAGE_F   (2 * 704)               // 1408 : 2 k-halves x 11 cands x 64
#define SDEC_F    (114 * 16)              // 1824
#define SH_OFF_F  (WC_F + STAGE_F + SDEC_F)
#define P_DSMEM   ((SH_OFF_F + 2048) * 4) // 217728 B

// k_pre dynamic smem: pitch-18 float2 tiles (16B-aligned rows, conflict-free LDS.128)
#define PP         18
#define PRE_W_F2   (256 * PP)
#define PRE_E_F2   (56 * PP)
#define PRE_DSMEM  ((PRE_W_F2 + PRE_E_F2) * 8)   // 44928 B

// ---------------------------------------------------------------------------
__device__ __align__(16) float g_h[2][H];
__device__ __align__(16) float g_c[H];
__device__ __align__(16) float g_pre[2][NROW][GATES];   // k-half partials
__device__ float g_part[2][12][NBLK];
__device__ unsigned g_cnt[32 * 8];

__device__ __forceinline__ float sigmoidf_(float v) { return 1.0f / (1.0f + expf(-v)); }

__device__ __forceinline__ void fma2(unsigned long long& d,
                                     unsigned long long a, unsigned long long b) {
    asm("fma.rn.f32x2 %0, %1, %2, %0;" : "+l"(d) : "l"(a), "l"(b));
}
__device__ __forceinline__ void unpk2(unsigned long long p, float& a, float& b) {
    asm("mov.b64 {%0, %1}, %2;" : "=f"(a), "=f"(b) : "l"(p));
}
__device__ __forceinline__ void lds128_2ull(unsigned long long& a, unsigned long long& b,
                                            const void* p) {
    uint32_t addr = (uint32_t)__cvta_generic_to_shared(p);
    asm("ld.shared.v2.u64 {%0, %1}, [%2];" : "=l"(a), "=l"(b) : "r"(addr));
}
__device__ __forceinline__ void cpasync16(const float* smem_dst, const float* gsrc) {
    uint32_t d = (uint32_t)__cvta_generic_to_shared(smem_dst);
    asm volatile("cp.async.cg.shared.global [%0], [%1], 16;" :: "r"(d), "l"(gsrc));
}

// ---------------------------------------------------------------------------
// Non-flushing grid barrier: 32 padded counters, NBLK/32 = 4 arrivals each.
// Counters zeroed by k_pre block 0.
// ---------------------------------------------------------------------------
__device__ __forceinline__ void gsync(unsigned target4) {
    __syncthreads();
    if (threadIdx.x == 0) {
        asm volatile("red.release.gpu.global.add.u32 [%0], %1;"
                     :: "l"(&g_cnt[(blockIdx.x & 31) * 8]), "r"(1u) : "memory");
    }
    if (threadIdx.x < 32) {
        const unsigned* cp = &g_cnt[threadIdx.x * 8];
        unsigned v;
        while (true) {
            asm volatile("ld.acquire.gpu.global.u32 %0, [%1];" : "=r"(v) : "l"(cp) : "memory");
            if (v >= target4) break;
            __nanosleep(40);
        }
    }
    __syncthreads();
}

// ---------------------------------------------------------------------------
// Precompute GEMM: 128 blocks x 512 threads, ONE block/SM, perfectly balanced.
// Tile per block: 256n x 56m x 1024k (nb 0..31, mb 0..1, kb 0..1).
// Thread grid 64 n-cols x 8 m-groups; thread tile 7m x 4n (56 packed accs).
// E-tiles load directly from encoder tables (static row map).
// ---------------------------------------------------------------------------
__global__ __launch_bounds__(512, 1)
void k_pre(const float* __restrict__ Wih,
           const float* __restrict__ b_ih, const float* __restrict__ b_hh,
           const float* __restrict__ enc_act, const float* __restrict__ enc_block) {
    extern __shared__ float2 dynp[];
    float2* Wt2 = dynp;                   // [256][PP]
    float2* Es2 = dynp + PRE_W_F2;        // [56][PP]
    __shared__ const float* srow[56];

    const int t = threadIdx.x;
    const int c6 = t & 63, r = t >> 6;

    const int bid = blockIdx.x;
    const int nb = bid & 31, mb = (bid >> 5) & 1, kb = bid >> 6;
    const int n_base = nb * 256, m_base = mb * 56, k_base = kb * 1024;

    if (bid == 0 && t < 32 * 8) g_cnt[t] = 0u;

    if (t < 56) {
        int m = m_base + t;
        int u = 1, base = 0, cnt = 4;
        while (u < 22 && m >= base + cnt) { base += cnt; ++u; cnt = (u & 1) ? 4 : (u >> 1); }
        const float* src;
        if (m >= base + cnt) {
            src = enc_act;   // pad rows 110,111
        } else {
            int o = m - base;
            if (u & 1) src = enc_act   + ((size_t)((u - 1) >> 1) * 4        + o) * H;
            else       src = enc_block + ((size_t)((u >> 1) - 1) * (NB - 1) + o) * H;
        }
        srow[t] = src;
    }
    __syncthreads();

    unsigned long long acc[7][4];
#pragma unroll
    for (int j = 0; j < 7; j++)
#pragma unroll
        for (int i = 0; i < 4; i++) acc[j][i] = 0ull;

    // W load mapping: 2 threads per n-row, 64B each
    const int wrow_l = t >> 1, whalf = t & 1;
    const float* wsrc_row = Wih + (size_t)(n_base + wrow_l) * H;
    // E load mapping: threads 0..447, one float4 each
    const int erow = t >> 3, eq = t & 7;

    float4 wst[4];
    float4 est;
    {
#pragma unroll
        for (int q = 0; q < 4; q++)
            wst[q] = __ldcg((const float4*)(wsrc_row + k_base + whalf * 16 + 4 * q));
        if (t < 448)
            est = __ldcg((const float4*)(srow[erow] + k_base + 4 * eq));
    }

    for (int kt = 0; kt < 1024; kt += 32) {
        // commit staged regs to smem
        {
#pragma unroll
            for (int q = 0; q < 4; q++)
                *(float4*)&Wt2[wrow_l * PP + whalf * 8 + 2 * q] = wst[q];
            if (t < 448)
                *(float4*)&Es2[erow * PP + 2 * eq] = est;
        }
        __syncthreads();

        // issue loads for next slab
        if (kt + 32 < 1024) {
            const int k0 = k_base + kt + 32;
#pragma unroll
            for (int q = 0; q < 4; q++)
                wst[q] = __ldcg((const float4*)(wsrc_row + k0 + whalf * 16 + 4 * q));
            if (t < 448)
                est = __ldcg((const float4*)(srow[erow] + k0 + 4 * eq));
        }

        // compute: two kk2 slices per LDS.128
#pragma unroll
        for (int kk2 = 0; kk2 < 16; kk2 += 2) {
            unsigned long long wa[4], wb[4], ea[7], eb[7];
#pragma unroll
            for (int i = 0; i < 4; i++)
                lds128_2ull(wa[i], wb[i], &Wt2[(c6 + 64 * i) * PP + kk2]);
#pragma unroll
            for (int j = 0; j < 7; j++)
                lds128_2ull(ea[j], eb[j], &Es2[(r * 7 + j) * PP + kk2]);
#pragma unroll
            for (int j = 0; j < 7; j++)
#pragma unroll
                for (int i = 0; i < 4; i++)
                    fma2(acc[j][i], wa[i], ea[j]);
#pragma unroll
            for (int j = 0; j < 7; j++)
#pragma unroll
                for (int i = 0; i < 4; i++)
                    fma2(acc[j][i], wb[i], eb[j]);
        }
        __syncthreads();
    }

#pragma unroll
    for (int j = 0; j < 7; j++) {
        int m = m_base + r * 7 + j;
#pragma unroll
        for (int i = 0; i < 4; i++) {
            int n = n_base + c6 + 64 * i;
            float lo, hi;
            unpk2(acc[j][i], lo, hi);
            float v = lo + hi;
            if (kb == 0) v += b_ih[n] + b_hh[n];
            g_pre[kb][m][n] = v;
        }
    }
}

// ---------------------------------------------------------------------------
__device__ __forceinline__ const float* dec_for(int s, const float* da,
                                                const float* db, int& ncls) {
    if (s == 0) { ncls = 4; return da; }
    if (s & 1)  { int bid = (s + 1) >> 1; ncls = bid;
                  return db + (size_t)(bid - 1) * (NB - 1) * H; }
    ncls = 4; return da + (size_t)(s >> 1) * 4 * H;
}

// ---------------------------------------------------------------------------
// Persistent kernel: 128 blocks x 512 threads (1/SM, 128 regs/thread).
// Candidate pre-rows prefetched via cp.async as RAW 2 k-halves into a single
// staging buffer; the 16-thread tail sums the halves (deterministic order).
// ---------------------------------------------------------------------------
__global__ __launch_bounds__(NTHR, 1)
void k_persist(const float* __restrict__ Whh,
               const float* __restrict__ b_ih, const float* __restrict__ b_hh,
               const float* __restrict__ dec_act, const float* __restrict__ dec_block,
               float* __restrict__ out, int out_size) {
    extern __shared__ float dyn[];
    float4* wc4   = (float4*)dyn;                    // [64][KC4]
    float*  stage = dyn + WC_F;                      // [2][704]
    float*  sdec  = stage + STAGE_F;                 // [114][16]
    float4* sh4   = (float4*)(dyn + SH_OFF_F);       // [512] staged h

    __shared__ float sg[64];
    __shared__ float slog[12];
    __shared__ float sunit[16];
    __shared__ float scell[16];

    const int bid = blockIdx.x, t = threadIdx.x;
    const int lane = t & 31, warp = t >> 5;
    const int j0 = bid * 16;
    const float4* W4 = (const float4*)Whh;

    const int wrow = warp * 4;
    const int gte = warp >> 2;
    const int un0 = (warp & 3) * 4;
    const float4* wp0 = W4 + (size_t)(gte * H + j0 + un0 + 0) * (H / 4);
    const float4* wp1 = W4 + (size_t)(gte * H + j0 + un0 + 1) * (H / 4);
    const float4* wp2 = W4 + (size_t)(gte * H + j0 + un0 + 2) * (H / 4);
    const float4* wp3 = W4 + (size_t)(gte * H + j0 + un0 + 3) * (H / 4);

    // ---- startup loads ----
    for (int idx = t; idx < 64 * KC4; idx += NTHR) {
        int R = idx / KC4, q = idx - R * KC4;
        size_t grow = (size_t)((R >> 4) * H + j0 + (R & 15));
        wc4[R * KC4 + q] = __ldcg(&W4[grow * (H / 4) + q]);
    }
    for (int e = t; e < SDEC_F; e += NTHR) {
        int cr = e >> 4, u = e & 15;
        int off = 0, nc = 0;
        const float* dp = dec_act;
        for (int s = 0; s <= 22; s++) {
            dp = dec_for(s, dec_act, dec_block, nc);
            if (cr < off + nc) break;
            off += nc;
        }
        int cls = cr - off;
        sdec[e] = __ldcg(&dp[(size_t)cls * H + j0 + u]);
    }
    // step-1 candidates: raw halves into stage
    for (int idx = t; idx < 2 * 4 * 64; idx += NTHR) {
        int q = idx >> 8, rem = idx & 255;
        int cd = rem >> 6, c = rem & 63;
        stage[q * 704 + cd * 64 + c] =
            __ldcg(&g_pre[q][cd][(size_t)(c >> 4) * H + j0 + (c & 15)]);
    }

    // register-resident W slice: rows wrow..wrow+3, j = JR0..JR1-1
    float4 wr0[JR1 - JR0], wr1[JR1 - JR0], wr2[JR1 - JR0], wr3[JR1 - JR0];
#pragma unroll
    for (int jj = 0; jj < JR1 - JR0; jj++) {
        const int idx = lane + 32 * (JR0 + jj);
        wr0[jj] = __ldcg(&wp0[idx]);
        wr1[jj] = __ldcg(&wp1[idx]);
        wr2[jj] = __ldcg(&wp2[idx]);
        wr3[jj] = __ldcg(&wp3[idx]);
    }

    // ---- step 0: gates = biases ----
    if (t < 16) {
        int j = j0 + t;
        float gi = b_ih[j        ] + b_hh[j        ];
        float gg = b_ih[2 * H + j] + b_hh[2 * H + j];
        float go = b_ih[3 * H + j] + b_hh[3 * H + j];
        float c2 = sigmoidf_(gi) * tanhf(gg);
        float h2 = sigmoidf_(go) * tanhf(c2);
        scell[t] = c2;
        sunit[t] = h2;
        __stcg(&g_h[0][j], h2);
    }
    __syncthreads();
    if (warp < 4) {
        float v = (lane < 16) ? sunit[lane] * sdec[warp * 16 + lane] : 0.0f;
        v += __shfl_down_sync(0xffffffffu, v, 8);
        v += __shfl_down_sync(0xffffffffu, v, 4);
        v += __shfl_down_sync(0xffffffffu, v, 2);
        v += __shfl_down_sync(0xffffffffu, v, 1);
        if (lane == 0) __stcg(&g_part[1][warp][bid], v);
    }

    unsigned phase = 1;
    gsync(phase * 4);

    // ---- 22 fused steps ----
    int cand_base = 0, ncand = 4, doff = 4;
    for (int s = 1; s <= 22; s++) {
        const int parity = s & 1, pr = s & 1, pw = (s + 1) & 1;

        // stage h into smem
        sh4[t] = __ldcg(&((const float4*)g_h[parity ^ 1])[t]);

        // prologue: per-class sums of 128 block-partials
        if (warp < ncand) {
            const float* p = g_part[pr][warp];
            float a = __ldcg(&p[lane]) + __ldcg(&p[lane + 32])
                    + __ldcg(&p[lane + 64]) + __ldcg(&p[lane + 96]);
            a += __shfl_down_sync(0xffffffffu, a, 16);
            a += __shfl_down_sync(0xffffffffu, a, 8);
            a += __shfl_down_sync(0xffffffffu, a, 4);
            a += __shfl_down_sync(0xffffffffu, a, 2);
            a += __shfl_down_sync(0xffffffffu, a, 1);
            if (lane == 0) slog[warp] = a;
        }
        __syncthreads();

        // GEMV: warp computes rows wrow..wrow+3 fully
        float a0 = 0.f, a1 = 0.f, a2 = 0.f, a3 = 0.f;

        // streamed region (j = JS0..15)
#pragma unroll
        for (int j = JS0; j < 16; j++) {
            const int idx = lane + 32 * j;
            float4 w0 = __ldcg(&wp0[idx]);
            float4 w1 = __ldcg(&wp1[idx]);
            float4 w2 = __ldcg(&wp2[idx]);
            float4 w3 = __ldcg(&wp3[idx]);
            float4 hv = sh4[idx];
            a0 += hv.x * w0.x + hv.y * w0.y + hv.z * w0.z + hv.w * w0.w;
            a1 += hv.x * w1.x + hv.y * w1.y + hv.z * w1.z + hv.w * w1.w;
            a2 += hv.x * w2.x + hv.y * w2.y + hv.z * w2.z + hv.w * w2.w;
            a3 += hv.x * w3.x + hv.y * w3.y + hv.z * w3.z + hv.w * w3.w;
        }
        // register-resident region (j = JR0..JR1-1)
#pragma unroll
        for (int jj = 0; jj < JR1 - JR0; jj++) {
            const int idx = lane + 32 * (JR0 + jj);
            float4 hv = sh4[idx];
            a0 += hv.x * wr0[jj].x + hv.y * wr0[jj].y + hv.z * wr0[jj].z + hv.w * wr0[jj].w;
            a1 += hv.x * wr1[jj].x + hv.y * wr1[jj].y + hv.z * wr1[jj].z + hv.w * wr1[jj].w;
            a2 += hv.x * wr2[jj].x + hv.y * wr2[jj].y + hv.z * wr2[jj].z + hv.w * wr2[jj].w;
            a3 += hv.x * wr3[jj].x + hv.y * wr3[jj].y + hv.z * wr3[jj].z + hv.w * wr3[jj].w;
        }
        // smem-cached region (j = 0..5)
#pragma unroll
        for (int j = 0; j < 6; j++) {
            const int idx = lane + 32 * j;
            float4 hv = sh4[idx];
            float4 w0 = wc4[(wrow + 0) * KC4 + idx];
            float4 w1 = wc4[(wrow + 1) * KC4 + idx];
            float4 w2 = wc4[(wrow + 2) * KC4 + idx];
            float4 w3 = wc4[(wrow + 3) * KC4 + idx];
            a0 += hv.x * w0.x + hv.y * w0.y + hv.z * w0.z + hv.w * w0.w;
            a1 += hv.x * w1.x + hv.y * w1.y + hv.z * w1.z + hv.w * w1.w;
            a2 += hv.x * w2.x + hv.y * w2.y + hv.z * w2.z + hv.w * w2.w;
            a3 += hv.x * w3.x + hv.y * w3.y + hv.z * w3.z + hv.w * w3.w;
        }

#pragma unroll
        for (int o = 16; o > 0; o >>= 1) {
            a0 += __shfl_down_sync(0xffffffffu, a0, o);
            a1 += __shfl_down_sync(0xffffffffu, a1, o);
            a2 += __shfl_down_sync(0xffffffffu, a2, o);
            a3 += __shfl_down_sync(0xffffffffu, a3, o);
        }
        if (lane == 0) {
            sg[wrow + 0] = a0; sg[wrow + 1] = a1;
            sg[wrow + 2] = a2; sg[wrow + 3] = a3;
        }
        asm volatile("cp.async.wait_group 0;" ::: "memory");
        __syncthreads();

        // tail: 16 threads do argmax + half-sum + gate math (pure smem)
        if (t < 16) {
            int lc = 0;
            {
                float bv = slog[0];
                for (int cc = 1; cc < ncand; cc++)
                    if (slog[cc] > bv) { bv = slog[cc]; lc = cc; }
            }
            const float* cp = stage + lc * 64;
            float gi = sg[t]      + (cp[t]      + cp[704 + t]);
            float gf = sg[16 + t] + (cp[16 + t] + cp[704 + 16 + t]);
            float gg = sg[32 + t] + (cp[32 + t] + cp[704 + 32 + t]);
            float go = sg[48 + t] + (cp[48 + t] + cp[704 + 48 + t]);
            float c2 = sigmoidf_(gf) * scell[t] + sigmoidf_(gi) * tanhf(gg);
            float h2 = sigmoidf_(go) * tanhf(c2);
            scell[t] = c2;
            sunit[t] = h2;
            __stcg(&g_h[parity][j0 + t], h2);
            if (s == 22) __stcg(&g_c[j0 + t], c2);
        }
        __syncthreads();   // tail reads of stage complete before cp.async overwrite

        // epilogue: decode partials from smem decoder rows
        int ncls;
        dec_for(s, dec_act, dec_block, ncls);
        if (warp < ncls) {
            float v = (lane < 16) ? sunit[lane] * sdec[(doff + warp) * 16 + lane] : 0.0f;
            v += __shfl_down_sync(0xffffffffu, v, 8);
            v += __shfl_down_sync(0xffffffffu, v, 4);
            v += __shfl_down_sync(0xffffffffu, v, 2);
            v += __shfl_down_sync(0xffffffffu, v, 1);
            if (lane == 0) __stcg(&g_part[pw][warp][bid], v);
        }

        // cp.async prefetch of next step's candidate halves (register-free)
        int nb_next = cand_base + ncand;
        if (s < 22) {
            int chunks = ncls * 32;               // (cd, c4) x 2 halves
            for (int ch = t; ch < chunks; ch += NTHR) {
                int q = ch & 1, rest = ch >> 1;
                int cd = rest >> 4, c4 = rest & 15;
                int g = c4 >> 2, qf = c4 & 3;
                cpasync16(stage + q * 704 + cd * 64 + g * 16 + qf * 4,
                          &g_pre[q][nb_next + cd][(size_t)g * H + j0 + qf * 4]);
            }
        }
        asm volatile("cp.async.commit_group;" ::: "memory");

        cand_base = nb_next;
        ncand = ncls;
        doff += ncls;

        ++phase;
        gsync(phase * 4);
    }

    // ---- final argmax ----
    if (warp < 4) {
        const float* p = g_part[1][warp];
        float a = __ldcg(&p[lane]) + __ldcg(&p[lane + 32])
                + __ldcg(&p[lane + 64]) + __ldcg(&p[lane + 96]);
        a += __shfl_down_sync(0xffffffffu, a, 16);
        a += __shfl_down_sync(0xffffffffu, a, 8);
        a += __shfl_down_sync(0xffffffffu, a, 4);
        a += __shfl_down_sync(0xffffffffu, a, 2);
        a += __shfl_down_sync(0xffffffffu, a, 1);
        if (lane == 0) slog[warp] = a;
    }
    __syncthreads();

    int best = 0;
    {
        float bv = slog[0];
        for (int cc = 1; cc < 4; cc++)
            if (slog[cc] > bv) { bv = slog[cc]; best = cc; }
    }

    // ---- stage final h, c into smem, then float4 output broadcast ----
    float* hbuf = dyn;
    float* cbuf = dyn + 2048;
    {
        float4* hb4 = (float4*)hbuf;
        float4* cb4 = (float4*)cbuf;
        hb4[t] = __ldcg(&((const float4*)g_h[0])[t]);
        cb4[t] = __ldcg(&((const float4*)g_c)[t]);
    }
    __syncthreads();

    const float fidx = (float)best;
    const long HB = (long)B * H;
    const long n4 = out_size >> 2;
    float4* out4 = (float4*)out;
    for (long i4 = (long)bid * NTHR + t; i4 < n4; i4 += (long)NBLK * NTHR) {
        long i = i4 << 2;
        float4 v;
        if (i < B) {
            v = make_float4(fidx, fidx, fidx, fidx);
        } else if (i < B + HB) {
            v = *(const float4*)&hbuf[(i - B) & (H - 1)];
        } else {
            v = *(const float4*)&cbuf[(i - B - HB) & (H - 1)];
        }
        __stcs(&out4[i4], v);
    }
    for (long i = (n4 << 2) + (long)bid * NTHR + t; i < out_size; i += (long)NBLK * NTHR) {
        float v;
        if (i < B)               v = fidx;
        else if (i < B + HB)     v = hbuf[(i - B) & (H - 1)];
        else if (i < B + 2 * HB) v = cbuf[(i - B - HB) & (H - 1)];
        else                     v = 0.0f;
        __stcs(out + i, v);
    }
}

// ---------------------------------------------------------------------------
extern "C" void kernel_launch(void* const* d_in, const int* in_sizes, int n_in,
                              void* d_out, int out_size) {
    (void)in_sizes; (void)n_in;
    const float* Wih       = (const float*)d_in[1];
    const float* Whh       = (const float*)d_in[2];
    const float* b_ih      = (const float*)d_in[3];
    const float* b_hh      = (const float*)d_in[4];
    const float* enc_act   = (const float*)d_in[5];
    const float* enc_block = (const float*)d_in[6];
    const float* dec_act   = (const float*)d_in[7];
    const float* dec_block = (const float*)d_in[8];

    static int attr_done = 0;
    if (!attr_done) {
        cudaFuncSetAttribute(k_persist, cudaFuncAttributeMaxDynamicSharedMemorySize, P_DSMEM);
        cudaFuncSetAttribute(k_pre, cudaFuncAttributeMaxDynamicSharedMemorySize, PRE_DSMEM);
        attr_done = 1;
    }

    k_pre<<<NBLK, 512, PRE_DSMEM>>>(Wih, b_ih, b_hh, enc_act, enc_block);
    k_persist<<<NBLK, NTHR, P_DSMEM>>>(Whh, b_ih, b_hh, dec_act, dec_block,
                                       (float*)d_out, out_size);
}

// round 17
// speedup vs baseline: 1.2286x; 1.1413x over previous
#include <cuda_runtime.h>
#include <cstddef>
#include <cstdint>

#define H     2048
#define B     1024
#define NB    12
#define NROW  112
#define GATES 8192
#define NBLK  128                 // blocks (1/SM)
#define NTHR  512
#define KC4   192                 // float4 k-prefix of each W_hh row in smem (j<6)
#define JR0   6                   // register-resident j range [JR0, JR1)
#define JR1   10
#define JS0   10                  // streamed j range [JS0, 16)

// dynamic smem layout (floats)
#define WC_F       (64 * KC4 * 4)          // 49152
#define STAGE_F    (2 * 704)               // 1408
#define SDEC_F     (114 * 16)              // 1824
#define SH_OFF_F   (WC_F + STAGE_F + SDEC_F)
#define TOTAL_F    (SH_OFF_F + 2048)       // 54432
#define P_DSMEM    (TOTAL_F * 4)           // 217728 B

// GEMM phase: double-buffered tiles at the END of the smem region
#define PP          18                      // float2 pitch per tile row
#define GEMM_W_F2   (256 * PP)              // 4608
#define GEMM_E_F2   (56 * PP)               // 1008
#define GEMM_BUF_F2 (GEMM_W_F2 + GEMM_E_F2) // 5616
#define GEMM_OFF_F  (TOTAL_F - 2 * GEMM_BUF_F2 * 2)  // 54432-22464 = 31968
#define PRELOAD_N   (GEMM_OFF_F / 4)        // 7992 float4s of wc4 safe to preload

// ---------------------------------------------------------------------------
__device__ __align__(16) float g_h[2][H];
__device__ __align__(16) float g_c[H];
__device__ __align__(16) float g_pre[2][NROW][GATES];   // k-half partials
__device__ float g_part[2][12][NBLK];
__device__ unsigned g_cnt[32 * 8];                      // monotonic across launches

__device__ __forceinline__ float sigmoidf_(float v) { return 1.0f / (1.0f + expf(-v)); }

__device__ __forceinline__ void fma2(unsigned long long& d,
                                     unsigned long long a, unsigned long long b) {
    asm("fma.rn.f32x2 %0, %1, %2, %0;" : "+l"(d) : "l"(a), "l"(b));
}
__device__ __forceinline__ void unpk2(unsigned long long p, float& a, float& b) {
    asm("mov.b64 {%0, %1}, %2;" : "=f"(a), "=f"(b) : "l"(p));
}
__device__ __forceinline__ void lds128_2ull(unsigned long long& a, unsigned long long& b,
                                            const void* p) {
    uint32_t addr = (uint32_t)__cvta_generic_to_shared(p);
    asm("ld.shared.v2.u64 {%0, %1}, [%2];" : "=l"(a), "=l"(b) : "r"(addr));
}
__device__ __forceinline__ void cpasync16(const float* smem_dst, const float* gsrc) {
    uint32_t d = (uint32_t)__cvta_generic_to_shared(smem_dst);
    asm volatile("cp.async.cg.shared.global [%0], [%1], 16;" :: "r"(d), "l"(gsrc));
}

// ---------------------------------------------------------------------------
// Grid barrier with monotonic counters (epoch base read at kernel start).
// 23 phases x 4 arrivals per counter per launch = 92/launch.
// ---------------------------------------------------------------------------
__device__ __forceinline__ void gsync(unsigned phase, const unsigned* sbase) {
    __syncthreads();
    if (threadIdx.x == 0) {
        asm volatile("red.release.gpu.global.add.u32 [%0], %1;"
                     :: "l"(&g_cnt[(blockIdx.x & 31) * 8]), "r"(1u) : "memory");
    }
    if (threadIdx.x < 32) {
        const unsigned* cp = &g_cnt[threadIdx.x * 8];
        const unsigned tgt = sbase[threadIdx.x] + phase * 4;
        unsigned v;
        while (true) {
            asm volatile("ld.acquire.gpu.global.u32 %0, [%1];" : "=r"(v) : "l"(cp) : "memory");
            if (v >= tgt) break;
            __nanosleep(40);
        }
    }
    __syncthreads();
}

// ---------------------------------------------------------------------------
__device__ __forceinline__ const float* dec_for(int s, const float* da,
                                                const float* db, int& ncls) {
    if (s == 0) { ncls = 4; return da; }
    if (s & 1)  { int bid = (s + 1) >> 1; ncls = bid;
                  return db + (size_t)(bid - 1) * (NB - 1) * H; }
    ncls = 4; return da + (size_t)(s >> 1) * 4 * H;
}

// ---------------------------------------------------------------------------
// ONE kernel: GEMM phase (precompute W_ih@E) -> persist phase (23 LSTM steps).
// 128 blocks x 512 threads, 1/SM.
// ---------------------------------------------------------------------------
__global__ __launch_bounds__(NTHR, 1)
void k_all(const float* __restrict__ Wih, const float* __restrict__ Whh,
           const float* __restrict__ b_ih, const float* __restrict__ b_hh,
           const float* __restrict__ enc_act, const float* __restrict__ enc_block,
           const float* __restrict__ dec_act, const float* __restrict__ dec_block,
           float* __restrict__ out, int out_size) {
    extern __shared__ float dyn[];
    float4* wc4   = (float4*)dyn;                    // [64][KC4]
    float*  stage = dyn + WC_F;                      // [2][704]
    float*  sdec  = stage + STAGE_F;                 // [114][16]
    float4* sh4   = (float4*)(dyn + SH_OFF_F);       // [512]

    __shared__ float sg[64];
    __shared__ float slog[12];
    __shared__ float sunit[16];
    __shared__ float scell[16];
    __shared__ unsigned sbase[32];
    __shared__ const float* srow[56];

    const int bid = blockIdx.x, t = threadIdx.x;
    const int lane = t & 31, warp = t >> 5;
    const int j0 = bid * 16;
    const float4* W4 = (const float4*)Whh;

    // epoch base for the monotonic grid barrier (must precede any arrival)
    if (t < 32) sbase[t] = (*(volatile unsigned*)&g_cnt[t * 8] / 92u) * 92u;

    // =======================================================================
    // Phase 1: GEMM tile bid : 256n x 56m x 1024k, cp.async double-buffered.
    // W_hh wc4 prefix [0..PRELOAD_N) preloads via cp.async interleaved.
    // =======================================================================
    {
        const int nb = bid & 31, mb = (bid >> 5) & 1, kb = bid >> 6;
        const int n_base = nb * 256, m_base = mb * 56, k_base = kb * 1024;
        const int c6 = t & 63, r = t >> 6;

        if (t < 56) {
            int m = m_base + t;
            int u = 1, base = 0, cnt = 4;
            while (u < 22 && m >= base + cnt) { base += cnt; ++u; cnt = (u & 1) ? 4 : (u >> 1); }
            const float* src;
            if (m >= base + cnt) {
                src = enc_act;   // pad rows 110,111
            } else {
                int o = m - base;
                if (u & 1) src = enc_act   + ((size_t)((u - 1) >> 1) * 4        + o) * H;
                else       src = enc_block + ((size_t)((u >> 1) - 1) * (NB - 1) + o) * H;
            }
            srow[t] = src;
        }
        __syncthreads();

        unsigned long long acc[7][4];
#pragma unroll
        for (int j = 0; j < 7; j++)
#pragma unroll
            for (int i = 0; i < 4; i++) acc[j][i] = 0ull;

        // tile slab loader (cp.async, no registers held)
        auto load_slab = [&](int kt, int p) {
            const int k0 = k_base + kt;
            float2* Wt2 = (float2*)(dyn + GEMM_OFF_F) + p * GEMM_BUF_F2;
            float2* Es2 = Wt2 + GEMM_W_F2;
#pragma unroll
            for (int x = 0; x < 4; x++) {
                int op = t + 512 * x;            // 0..2047
                int row = op >> 3, ch = op & 7;
                cpasync16((const float*)&Wt2[row * PP + 2 * ch],
                          Wih + (size_t)(n_base + row) * H + k0 + 4 * ch);
            }
            if (t < 448) {
                int row = t >> 3, ch = t & 7;
                cpasync16((const float*)&Es2[row * PP + 2 * ch], srow[row] + k0 + 4 * ch);
            }
        };
        // W_hh preload chunk for slab i (250 float4s/slab, 32 slabs = 8000 >= 7992)
        auto preload_chunk = [&](int i) {
            int idx = i * 250 + t;
            if (t < 250 && idx < PRELOAD_N) {
                int R = idx / KC4, q = idx - R * KC4;
                size_t grow = (size_t)((R >> 4) * H + j0 + (R & 15));
                cpasync16(dyn + idx * 4, (const float*)&W4[grow * (H / 4) + q]);
            }
        };

        load_slab(0, 0);
        asm volatile("cp.async.commit_group;" ::: "memory");

        for (int i = 0; i < 32; i++) {
            const int p = i & 1;
            if (i + 1 < 32) {
                load_slab((i + 1) * 32, p ^ 1);
                preload_chunk(i);
                asm volatile("cp.async.commit_group;" ::: "memory");
                asm volatile("cp.async.wait_group 1;" ::: "memory");
            } else {
                preload_chunk(i);
                asm volatile("cp.async.commit_group;" ::: "memory");
                asm volatile("cp.async.wait_group 1;" ::: "memory");  // slab 31 group is last-1
            }
            __syncthreads();

            const float2* Wt2 = (const float2*)(dyn + GEMM_OFF_F) + p * GEMM_BUF_F2;
            const float2* Es2 = Wt2 + GEMM_W_F2;
#pragma unroll
            for (int kk2 = 0; kk2 < 16; kk2 += 2) {
                unsigned long long wa[4], wb[4], ea[7], eb[7];
#pragma unroll
                for (int i2 = 0; i2 < 4; i2++)
                    lds128_2ull(wa[i2], wb[i2], &Wt2[(c6 + 64 * i2) * PP + kk2]);
#pragma unroll
                for (int j = 0; j < 7; j++)
                    lds128_2ull(ea[j], eb[j], &Es2[(r * 7 + j) * PP + kk2]);
#pragma unroll
                for (int j = 0; j < 7; j++)
#pragma unroll
                    for (int i2 = 0; i2 < 4; i2++)
                        fma2(acc[j][i2], wa[i2], ea[j]);
#pragma unroll
                for (int j = 0; j < 7; j++)
#pragma unroll
                    for (int i2 = 0; i2 < 4; i2++)
                        fma2(acc[j][i2], wb[i2], eb[j]);
            }
            __syncthreads();
        }

#pragma unroll
        for (int j = 0; j < 7; j++) {
            int m = m_base + r * 7 + j;
#pragma unroll
            for (int i = 0; i < 4; i++) {
                int n = n_base + c6 + 64 * i;
                float lo, hi;
                unpk2(acc[j][i], lo, hi);
                float v = lo + hi;
                if (kb == 0) v += b_ih[n] + b_hh[n];
                __stcg(&g_pre[kb][m][n], v);
            }
        }
        __syncthreads();   // GEMM tile smem region now reusable locally
    }

    // =======================================================================
    // Phase 2: persist startup (rest of wc4, sdec, wr regs, step 0)
    // =======================================================================
    for (int idx = PRELOAD_N + t; idx < 64 * KC4; idx += NTHR) {
        int R = idx / KC4, q = idx - R * KC4;
        size_t grow = (size_t)((R >> 4) * H + j0 + (R & 15));
        wc4[idx] = __ldcg(&W4[grow * (H / 4) + q]);
    }
    for (int e = t; e < SDEC_F; e += NTHR) {
        int cr = e >> 4, u = e & 15;
        int off = 0, nc = 0;
        const float* dp = dec_act;
        for (int s = 0; s <= 22; s++) {
            dp = dec_for(s, dec_act, dec_block, nc);
            if (cr < off + nc) break;
            off += nc;
        }
        int cls = cr - off;
        sdec[e] = __ldcg(&dp[(size_t)cls * H + j0 + u]);
    }

    const int wrow = warp * 4;
    const int gte = warp >> 2;
    const int un0 = (warp & 3) * 4;
    const float4* wp0 = W4 + (size_t)(gte * H + j0 + un0 + 0) * (H / 4);
    const float4* wp1 = W4 + (size_t)(gte * H + j0 + un0 + 1) * (H / 4);
    const float4* wp2 = W4 + (size_t)(gte * H + j0 + un0 + 2) * (H / 4);
    const float4* wp3 = W4 + (size_t)(gte * H + j0 + un0 + 3) * (H / 4);

    float4 wr0[JR1 - JR0], wr1[JR1 - JR0], wr2[JR1 - JR0], wr3[JR1 - JR0];
#pragma unroll
    for (int jj = 0; jj < JR1 - JR0; jj++) {
        const int idx = lane + 32 * (JR0 + jj);
        wr0[jj] = __ldcg(&wp0[idx]);
        wr1[jj] = __ldcg(&wp1[idx]);
        wr2[jj] = __ldcg(&wp2[idx]);
        wr3[jj] = __ldcg(&wp3[idx]);
    }

    // step 0: gates = biases
    if (t < 16) {
        int j = j0 + t;
        float gi = b_ih[j        ] + b_hh[j        ];
        float gg = b_ih[2 * H + j] + b_hh[2 * H + j];
        float go = b_ih[3 * H + j] + b_hh[3 * H + j];
        float c2 = sigmoidf_(gi) * tanhf(gg);
        float h2 = sigmoidf_(go) * tanhf(c2);
        scell[t] = c2;
        sunit[t] = h2;
        __stcg(&g_h[0][j], h2);
    }
    __syncthreads();
    if (warp < 4) {
        float v = (lane < 16) ? sunit[lane] * sdec[warp * 16 + lane] : 0.0f;
        v += __shfl_down_sync(0xffffffffu, v, 8);
        v += __shfl_down_sync(0xffffffffu, v, 4);
        v += __shfl_down_sync(0xffffffffu, v, 2);
        v += __shfl_down_sync(0xffffffffu, v, 1);
        if (lane == 0) __stcg(&g_part[1][warp][bid], v);
    }

    // all W_hh preload cp.asyncs done before first wc4 GEMV read
    asm volatile("cp.async.wait_group 0;" ::: "memory");

    unsigned phase = 1;
    gsync(phase, sbase);

    // =======================================================================
    // Phase 3: 22 fused steps
    // =======================================================================
    int cand_base = 0, ncand = 4, doff = 4;
    for (int s = 1; s <= 22; s++) {
        const int parity = s & 1, pr = s & 1, pw = (s + 1) & 1;

        // step-1 candidate prefetch must wait for the grid barrier (g_pre ready)
        if (s == 1) {
            for (int ch = t; ch < 4 * 32; ch += NTHR) {
                int q = ch & 1, rest = ch >> 1;
                int cd = rest >> 4, c4 = rest & 15;
                int g = c4 >> 2, qf = c4 & 3;
                cpasync16(stage + q * 704 + cd * 64 + g * 16 + qf * 4,
                          &g_pre[q][cd][(size_t)g * H + j0 + qf * 4]);
            }
            asm volatile("cp.async.commit_group;" ::: "memory");
        }

        // stage h into smem
        sh4[t] = __ldcg(&((const float4*)g_h[parity ^ 1])[t]);

        // prologue: per-class sums of 128 block-partials
        if (warp < ncand) {
            const float* p = g_part[pr][warp];
            float a = __ldcg(&p[lane]) + __ldcg(&p[lane + 32])
                    + __ldcg(&p[lane + 64]) + __ldcg(&p[lane + 96]);
            a += __shfl_down_sync(0xffffffffu, a, 16);
            a += __shfl_down_sync(0xffffffffu, a, 8);
            a += __shfl_down_sync(0xffffffffu, a, 4);
            a += __shfl_down_sync(0xffffffffu, a, 2);
            a += __shfl_down_sync(0xffffffffu, a, 1);
            if (lane == 0) slog[warp] = a;
        }
        __syncthreads();

        // GEMV: warp computes rows wrow..wrow+3 fully
        float a0 = 0.f, a1 = 0.f, a2 = 0.f, a3 = 0.f;

#pragma unroll
        for (int j = JS0; j < 16; j++) {
            const int idx = lane + 32 * j;
            float4 w0 = __ldcg(&wp0[idx]);
            float4 w1 = __ldcg(&wp1[idx]);
            float4 w2 = __ldcg(&wp2[idx]);
            float4 w3 = __ldcg(&wp3[idx]);
            float4 hv = sh4[idx];
            a0 += hv.x * w0.x + hv.y * w0.y + hv.z * w0.z + hv.w * w0.w;
            a1 += hv.x * w1.x + hv.y * w1.y + hv.z * w1.z + hv.w * w1.w;
            a2 += hv.x * w2.x + hv.y * w2.y + hv.z * w2.z + hv.w * w2.w;
            a3 += hv.x * w3.x + hv.y * w3.y + hv.z * w3.z + hv.w * w3.w;
        }
#pragma unroll
        for (int jj = 0; jj < JR1 - JR0; jj++) {
            const int idx = lane + 32 * (JR0 + jj);
            float4 hv = sh4[idx];
            a0 += hv.x * wr0[jj].x + hv.y * wr0[jj].y + hv.z * wr0[jj].z + hv.w * wr0[jj].w;
            a1 += hv.x * wr1[jj].x + hv.y * wr1[jj].y + hv.z * wr1[jj].z + hv.w * wr1[jj].w;
            a2 += hv.x * wr2[jj].x + hv.y * wr2[jj].y + hv.z * wr2[jj].z + hv.w * wr2[jj].w;
            a3 += hv.x * wr3[jj].x + hv.y * wr3[jj].y + hv.z * wr3[jj].z + hv.w * wr3[jj].w;
        }
#pragma unroll
        for (int j = 0; j < 6; j++) {
            const int idx = lane + 32 * j;
            float4 hv = sh4[idx];
            float4 w0 = wc4[(wrow + 0) * KC4 + idx];
            float4 w1 = wc4[(wrow + 1) * KC4 + idx];
            float4 w2 = wc4[(wrow + 2) * KC4 + idx];
            float4 w3 = wc4[(wrow + 3) * KC4 + idx];
            a0 += hv.x * w0.x + hv.y * w0.y + hv.z * w0.z + hv.w * w0.w;
            a1 += hv.x * w1.x + hv.y * w1.y + hv.z * w1.z + hv.w * w1.w;
            a2 += hv.x * w2.x + hv.y * w2.y + hv.z * w2.z + hv.w * w2.w;
            a3 += hv.x * w3.x + hv.y * w3.y + hv.z * w3.z + hv.w * w3.w;
        }

#pragma unroll
        for (int o = 16; o > 0; o >>= 1) {
            a0 += __shfl_down_sync(0xffffffffu, a0, o);
            a1 += __shfl_down_sync(0xffffffffu, a1, o);
            a2 += __shfl_down_sync(0xffffffffu, a2, o);
            a3 += __shfl_down_sync(0xffffffffu, a3, o);
        }
        if (lane == 0) {
            sg[wrow + 0] = a0; sg[wrow + 1] = a1;
            sg[wrow + 2] = a2; sg[wrow + 3] = a3;
        }
        asm volatile("cp.async.wait_group 0;" ::: "memory");
        __syncthreads();

        // tail: 16 threads do argmax + half-sum + gate math (pure smem)
        if (t < 16) {
            int lc = 0;
            {
                float bv = slog[0];
                for (int cc = 1; cc < ncand; cc++)
                    if (slog[cc] > bv) { bv = slog[cc]; lc = cc; }
            }
            const float* cp = stage + lc * 64;
            float gi = sg[t]      + (cp[t]      + cp[704 + t]);
            float gf = sg[16 + t] + (cp[16 + t] + cp[704 + 16 + t]);
            float gg = sg[32 + t] + (cp[32 + t] + cp[704 + 32 + t]);
            float go = sg[48 + t] + (cp[48 + t] + cp[704 + 48 + t]);
            float c2 = sigmoidf_(gf) * scell[t] + sigmoidf_(gi) * tanhf(gg);
            float h2 = sigmoidf_(go) * tanhf(c2);
            scell[t] = c2;
            sunit[t] = h2;
            __stcg(&g_h[parity][j0 + t], h2);
            if (s == 22) __stcg(&g_c[j0 + t], c2);
        }
        __syncthreads();   // tail reads of stage complete before cp.async overwrite

        // epilogue: decode partials from smem decoder rows
        int ncls;
        dec_for(s, dec_act, dec_block, ncls);
        if (warp < ncls) {
            float v = (lane < 16) ? sunit[lane] * sdec[(doff + warp) * 16 + lane] : 0.0f;
            v += __shfl_down_sync(0xffffffffu, v, 8);
            v += __shfl_down_sync(0xffffffffu, v, 4);
            v += __shfl_down_sync(0xffffffffu, v, 2);
            v += __shfl_down_sync(0xffffffffu, v, 1);
            if (lane == 0) __stcg(&g_part[pw][warp][bid], v);
        }

        // cp.async prefetch of next step's candidate halves (register-free)
        int nb_next = cand_base + ncand;
        if (s < 22) {
            int chunks = ncls * 32;               // (cd, c4) x 2 halves
            for (int ch = t; ch < chunks; ch += NTHR) {
                int q = ch & 1, rest = ch >> 1;
                int cd = rest >> 4, c4 = rest & 15;
                int g = c4 >> 2, qf = c4 & 3;
                cpasync16(stage + q * 704 + cd * 64 + g * 16 + qf * 4,
                          &g_pre[q][nb_next + cd][(size_t)g * H + j0 + qf * 4]);
            }
        }
        asm volatile("cp.async.commit_group;" ::: "memory");

        cand_base = nb_next;
        ncand = ncls;
        doff += ncls;

        ++phase;
        gsync(phase, sbase);
    }

    // ---- final argmax ----
    if (warp < 4) {
        const float* p = g_part[1][warp];
        float a = __ldcg(&p[lane]) + __ldcg(&p[lane + 32])
                + __ldcg(&p[lane + 64]) + __ldcg(&p[lane + 96]);
        a += __shfl_down_sync(0xffffffffu, a, 16);
        a += __shfl_down_sync(0xffffffffu, a, 8);
        a += __shfl_down_sync(0xffffffffu, a, 4);
        a += __shfl_down_sync(0xffffffffu, a, 2);
        a += __shfl_down_sync(0xffffffffu, a, 1);
        if (lane == 0) slog[warp] = a;
    }
    __syncthreads();

    int best = 0;
    {
        float bv = slog[0];
        for (int cc = 1; cc < 4; cc++)
            if (slog[cc] > bv) { bv = slog[cc]; best = cc; }
    }

    // ---- stage final h, c into smem, then float4 output broadcast ----
    float* hbuf = dyn;
    float* cbuf = dyn + 2048;
    {
        float4* hb4 = (float4*)hbuf;
        float4* cb4 = (float4*)cbuf;
        hb4[t] = __ldcg(&((const float4*)g_h[0])[t]);
        cb4[t] = __ldcg(&((const float4*)g_c)[t]);
    }
    __syncthreads();

    const float fidx = (float)best;
    const long HB = (long)B * H;
    const long n4 = out_size >> 2;
    float4* out4 = (float4*)out;
    for (long i4 = (long)bid * NTHR + t; i4 < n4; i4 += (long)NBLK * NTHR) {
        long i = i4 << 2;
        float4 v;
        if (i < B) {
            v = make_float4(fidx, fidx, fidx, fidx);
        } else if (i < B + HB) {
            v = *(const float4*)&hbuf[(i - B) & (H - 1)];
        } else {
            v = *(const float4*)&cbuf[(i - B - HB) & (H - 1)];
        }
        __stcs(&out4[i4], v);
    }
    for (long i = (n4 << 2) + (long)bid * NTHR + t; i < out_size; i += (long)NBLK * NTHR) {
        float v;
        if (i < B)               v = fidx;
        else if (i < B + HB)     v = hbuf[(i - B) & (H - 1)];
        else if (i < B + 2 * HB) v = cbuf[(i - B - HB) & (H - 1)];
        else                     v = 0.0f;
        __stcs(out + i, v);
    }
}

// ---------------------------------------------------------------------------
extern "C" void kernel_launch(void* const* d_in, const int* in_sizes, int n_in,
                              void* d_out, int out_size) {
    (void)in_sizes; (void)n_in;
    const float* Wih       = (const float*)d_in[1];
    const float* Whh       = (const float*)d_in[2];
    const float* b_ih      = (const float*)d_in[3];
    const float* b_hh      = (const float*)d_in[4];
    const float* enc_act   = (const float*)d_in[5];
    const float* enc_block = (const float*)d_in[6];
    const float* dec_act   = (const float*)d_in[7];
    const float* dec_block = (const float*)d_in[8];

    static int attr_done = 0;
    if (!attr_done) {
        cudaFuncSetAttribute(k_all, cudaFuncAttributeMaxDynamicSharedMemorySize, P_DSMEM);
        attr_done = 1;
    }

    k_all<<<NBLK, NTHR, P_DSMEM>>>(Wih, Whh, b_ih, b_hh, enc_act, enc_block,
                                   dec_act, dec_block, (float*)d_out, out_size);
}